// round 1
// baseline (speedup 1.0000x reference)
#include <cuda_runtime.h>
#include <math.h>

#define BB 4
#define TT 2048
#define BT (BB*TT)
#define DM 256
#define HH 8
#define DKk 32
#define DHid 1024
#define ND 8192
#define NL 4

// -------------------- scratch (device globals; no allocation allowed) ---------
__device__ float g_h  [BT*DM];
__device__ float g_q  [BT*DM];
__device__ float g_k  [BT*DM];
__device__ float g_v  [BT*DM];
__device__ float g_ov [BT*DM];
__device__ float g_y  [BT*DHid];
__device__ float g_tmp[BT*DM];
__device__ float g_wosum[DKk*DM];
__device__ int   g_is64;

// -------------------- helpers -------------------------------------------------
__device__ __forceinline__ float block_sum_256(float v, float* sbuf) {
    #pragma unroll
    for (int o = 16; o; o >>= 1) v += __shfl_xor_sync(0xffffffffu, v, o);
    int lane = threadIdx.x & 31, w = threadIdx.x >> 5;
    if (lane == 0) sbuf[w] = v;
    __syncthreads();
    if (threadIdx.x < 32) {
        float t = (lane < 8) ? sbuf[lane] : 0.f;
        #pragma unroll
        for (int o = 4; o; o >>= 1) t += __shfl_xor_sync(0xffffffffu, t, o);
        if (lane == 0) sbuf[0] = t;
    }
    __syncthreads();
    float r = sbuf[0];
    __syncthreads();
    return r;
}

// -------------------- index dtype probe ---------------------------------------
// If x is int64 (little-endian), the odd int32 words are all zero (values < 8192).
__global__ void detect_idx(const int* __restrict__ xi) {
    __shared__ int ok;
    if (threadIdx.x == 0) ok = 1;
    __syncthreads();
    if (xi[2 * threadIdx.x + 1] != 0) atomicAnd(&ok, 0);
    __syncthreads();
    if (threadIdx.x == 0) g_is64 = ok;
}

// -------------------- embedding + layernorm -----------------------------------
__global__ __launch_bounds__(256) void embed_ln(const int* __restrict__ xi,
                                                const float* __restrict__ emb,
                                                const float* __restrict__ pos) {
    __shared__ float sbuf[32];
    int token = blockIdx.x;
    int t = token % TT;
    int d = threadIdx.x;
    int idx = g_is64 ? xi[2 * token] : xi[token];
    float val = emb[(size_t)idx * DM + d] + pos[(size_t)t * DM + d];
    float m = block_sum_256(val, sbuf) * (1.f / DM);
    float c = val - m;
    float var = block_sum_256(c * c, sbuf) * (1.f / DM);
    g_h[(size_t)token * DM + d] = c * rsqrtf(var + 1e-5f);
}

// -------------------- generic tiled SGEMM 128x128x16 --------------------------
// BMODE 0: B row-major [K][N].  BMODE 1: B = per-head weights [n/32][K][n%32].
// EPI 0: C=acc.  EPI 1: C=relu(acc+bias[n]).  EPI 2: C=acc+bias[n].
template <int BMODE, int EPI>
__global__ __launch_bounds__(256) void sgemm(const float* __restrict__ A,
                                             const float* __restrict__ Bm,
                                             float* __restrict__ C,
                                             const float* __restrict__ bias,
                                             int M, int N, int K) {
    __shared__ float As[16][132];
    __shared__ float Bs[16][132];
    const int bm = blockIdx.y * 128;
    const int bn = blockIdx.x * 128;
    const int tid = threadIdx.x;
    const int row_base = (tid / 16) * 8;
    const int col_base = (tid % 16) * 8;

    float acc[8][8];
    #pragma unroll
    for (int i = 0; i < 8; i++)
        #pragma unroll
        for (int j = 0; j < 8; j++) acc[i][j] = 0.f;

    for (int k0 = 0; k0 < K; k0 += 16) {
        // load A tile (128 rows x 16 k) -> As[k][m]
        #pragma unroll
        for (int it = 0; it < 2; it++) {
            int f  = tid + it * 256;
            int r  = f >> 2;
            int c4 = (f & 3) * 4;
            float4 v = *(const float4*)(A + (size_t)(bm + r) * K + k0 + c4);
            As[c4 + 0][r] = v.x; As[c4 + 1][r] = v.y;
            As[c4 + 2][r] = v.z; As[c4 + 3][r] = v.w;
        }
        // load B tile (16 k x 128 n) -> Bs[k][n]
        #pragma unroll
        for (int it = 0; it < 2; it++) {
            int f  = tid + it * 256;
            int r  = f >> 5;
            int c4 = (f & 31) * 4;
            const float* bp;
            if (BMODE == 0) {
                bp = Bm + (size_t)(k0 + r) * N + bn + c4;
            } else {
                int n = bn + c4;
                bp = Bm + (size_t)(n >> 5) * ((size_t)K * 32) + (size_t)(k0 + r) * 32 + (n & 31);
            }
            float4 v = *(const float4*)bp;
            Bs[r][c4 + 0] = v.x; Bs[r][c4 + 1] = v.y;
            Bs[r][c4 + 2] = v.z; Bs[r][c4 + 3] = v.w;
        }
        __syncthreads();
        #pragma unroll
        for (int kk = 0; kk < 16; kk++) {
            float ra[8], rb[8];
            #pragma unroll
            for (int i = 0; i < 8; i++) ra[i] = As[kk][row_base + i];
            #pragma unroll
            for (int j = 0; j < 8; j++) rb[j] = Bs[kk][col_base + j];
            #pragma unroll
            for (int i = 0; i < 8; i++)
                #pragma unroll
                for (int j = 0; j < 8; j++) acc[i][j] += ra[i] * rb[j];
        }
        __syncthreads();
    }

    #pragma unroll
    for (int i = 0; i < 8; i++) {
        int m = bm + row_base + i;
        float o[8];
        #pragma unroll
        for (int j = 0; j < 8; j++) {
            int n = bn + col_base + j;
            float v = acc[i][j];
            if (EPI == 1) v = fmaxf(v + bias[n], 0.f);
            if (EPI == 2) v = v + bias[n];
            o[j] = v;
        }
        float4* cp = (float4*)(C + (size_t)m * N + bn + col_base);
        cp[0] = make_float4(o[0], o[1], o[2], o[3]);
        cp[1] = make_float4(o[4], o[5], o[6], o[7]);
    }
}

// -------------------- causal attention (exp-sum normalization) ----------------
// grid: (TT/64, BB*HH), 256 threads. Each thread: one query row, 8 v-dims.
__global__ __launch_bounds__(256) void attention(const float* __restrict__ q,
                                                 const float* __restrict__ k,
                                                 const float* __restrict__ v,
                                                 float* __restrict__ ov) {
    __shared__ float qs[64][33];
    __shared__ float ks[64][33];
    __shared__ float vs[64][33];
    __shared__ float s [64][65];

    const int bh = blockIdx.y;
    const int b  = bh >> 3, h = bh & 7;
    const int t0 = blockIdx.x * 64;
    const int tid = threadIdx.x;
    const int qi = tid >> 2;
    const int g  = tid & 3;

    // load q tile (64 x 32)
    for (int e = tid; e < 64 * 32; e += 256) {
        int r = e >> 5, d = e & 31;
        qs[r][d] = q[(size_t)(b * TT + t0 + r) * DM + h * DKk + d];
    }
    __syncthreads();

    // register-resident q row for this thread's query
    float qreg[32];
    #pragma unroll
    for (int kk = 0; kk < 32; kk++) qreg[kk] = qs[qi][kk];

    float acc[8];
    #pragma unroll
    for (int j = 0; j < 8; j++) acc[j] = 0.f;
    float ssum = 0.f;

    const int tg = t0 + qi;

    for (int o0 = 0; o0 <= t0; o0 += 64) {
        // load k/v tiles
        for (int e = tid; e < 64 * 32; e += 256) {
            int r = e >> 5, d = e & 31;
            size_t gidx = (size_t)(b * TT + o0 + r) * DM + h * DKk + d;
            ks[r][d] = k[gidx];
            vs[r][d] = v[gidx];
        }
        __syncthreads();

        // phase 1: scores (each thread: 16 keys for its query row)
        #pragma unroll 1
        for (int jj = 0; jj < 16; jj++) {
            int o = jj * 4 + g;
            float dot = 0.f;
            #pragma unroll
            for (int kk = 0; kk < 32; kk++) dot += qreg[kk] * ks[o][kk];
            float w = (o0 + o <= tg) ? __expf(fminf(dot, 50.f)) : 0.f;
            s[qi][o] = w;
        }
        __syncthreads();

        // phase 2: weighted V accumulation
        #pragma unroll 1
        for (int o = 0; o < 64; o++) {
            float w = s[qi][o];
            ssum += w;
            #pragma unroll
            for (int j = 0; j < 8; j++) acc[j] += w * vs[o][g * 8 + j];
        }
        __syncthreads();
    }

    float inv = 1.f / (ssum + 1e-10f);
    #pragma unroll
    for (int j = 0; j < 8; j++)
        ov[(size_t)(b * TT + tg) * DM + h * DKk + g * 8 + j] = acc[j] * inv;
}

// -------------------- sum wo over heads ---------------------------------------
__global__ void compute_wosum(const float* __restrict__ wo_layer) {
    int i = blockIdx.x * blockDim.x + threadIdx.x;
    if (i < DKk * DM) {
        float ssum = 0.f;
        #pragma unroll
        for (int hh = 0; hh < HH; hh++) ssum += wo_layer[(size_t)hh * DKk * DM + i];
        g_wosum[i] = ssum;
    }
}

// -------------------- fused: head-reduce + wo_sum proj + residual + LN --------
__global__ __launch_bounds__(256) void attn_out_ln(const float* __restrict__ ov) {
    __shared__ float row[DM];
    __shared__ float vsum[DKk];
    __shared__ float sbuf[32];
    int token = blockIdx.x;
    int d = threadIdx.x;
    row[d] = ov[(size_t)token * DM + d];
    __syncthreads();
    if (d < DKk) {
        float ssum = 0.f;
        #pragma unroll
        for (int hh = 0; hh < HH; hh++) ssum += row[hh * DKk + d];
        vsum[d] = ssum;
    }
    __syncthreads();
    float proj = 0.f;
    #pragma unroll
    for (int vv = 0; vv < DKk; vv++) proj += vsum[vv] * g_wosum[vv * DM + d];
    float val = g_h[(size_t)token * DM + d] + proj;   // AMUL == 1
    float m = block_sum_256(val, sbuf) * (1.f / DM);
    float c = val - m;
    float var = block_sum_256(c * c, sbuf) * (1.f / DM);
    g_h[(size_t)token * DM + d] = c * rsqrtf(var + 1e-5f);
}

// -------------------- residual + LN -------------------------------------------
__global__ __launch_bounds__(256) void ln_residual(const float* __restrict__ add) {
    __shared__ float sbuf[32];
    int token = blockIdx.x;
    int d = threadIdx.x;
    float val = g_h[(size_t)token * DM + d] + add[(size_t)token * DM + d];  // PMUL == 1
    float m = block_sum_256(val, sbuf) * (1.f / DM);
    float c = val - m;
    float var = block_sum_256(c * c, sbuf) * (1.f / DM);
    g_h[(size_t)token * DM + d] = c * rsqrtf(var + 1e-5f);
}

// -------------------- launch --------------------------------------------------
extern "C" void kernel_launch(void* const* d_in, const int* in_sizes, int n_in,
                              void* d_out, int out_size) {
    const int*   x     = (const int*)  d_in[0];
    const float* emb   = (const float*)d_in[1];
    const float* pos   = (const float*)d_in[2];
    const float* wq    = (const float*)d_in[3];
    const float* wk    = (const float*)d_in[4];
    const float* wv    = (const float*)d_in[5];
    const float* wo    = (const float*)d_in[6];
    const float* mlp0  = (const float*)d_in[7];
    const float* mlpb  = (const float*)d_in[8];
    const float* mlp1  = (const float*)d_in[9];
    const float* unemb = (const float*)d_in[10];
    const float* bias  = (const float*)d_in[11];
    float* out = (float*)d_out;

    float *h_, *q_, *k_, *v_, *ov_, *y_, *tmp_;
    cudaGetSymbolAddress((void**)&h_,   g_h);
    cudaGetSymbolAddress((void**)&q_,   g_q);
    cudaGetSymbolAddress((void**)&k_,   g_k);
    cudaGetSymbolAddress((void**)&v_,   g_v);
    cudaGetSymbolAddress((void**)&ov_,  g_ov);
    cudaGetSymbolAddress((void**)&y_,   g_y);
    cudaGetSymbolAddress((void**)&tmp_, g_tmp);

    detect_idx<<<1, 64>>>(x);
    embed_ln<<<BT, 256>>>(x, emb, pos);

    for (int l = 0; l < NL; l++) {
        const float* wql = wq + (size_t)l * HH * DM * DKk;
        const float* wkl = wk + (size_t)l * HH * DM * DKk;
        const float* wvl = wv + (size_t)l * HH * DM * DKk;
        const float* wol = wo + (size_t)l * HH * DKk * DM;

        compute_wosum<<<32, 256>>>(wol);

        dim3 gqkv(DM / 128, BT / 128);
        sgemm<1, 0><<<gqkv, 256>>>(h_, wql, q_, nullptr, BT, DM, DM);
        sgemm<1, 0><<<gqkv, 256>>>(h_, wkl, k_, nullptr, BT, DM, DM);
        sgemm<1, 0><<<gqkv, 256>>>(h_, wvl, v_, nullptr, BT, DM, DM);

        attention<<<dim3(TT / 64, BB * HH), 256>>>(q_, k_, v_, ov_);
        attn_out_ln<<<BT, 256>>>(ov_);

        sgemm<0, 1><<<dim3(DHid / 128, BT / 128), 256>>>(
            h_, mlp0 + (size_t)l * DM * DHid, y_, mlpb + (size_t)l * DHid, BT, DHid, DM);
        sgemm<0, 0><<<dim3(DM / 128, BT / 128), 256>>>(
            y_, mlp1 + (size_t)l * DHid * DM, tmp_, nullptr, BT, DM, DHid);
        ln_residual<<<BT, 256>>>(tmp_);
    }

    sgemm<0, 2><<<dim3(ND / 128, BT / 128), 256>>>(h_, unemb, out, bias, BT, ND, DM);
}

// round 2
// speedup vs baseline: 1.1855x; 1.1855x over previous
#include <cuda_runtime.h>
#include <cuda_bf16.h>
#include <math.h>

#define BB 4
#define TT 2048
#define BT (BB*TT)
#define DM 256
#define HH 8
#define DKk 32
#define DHid 1024
#define ND 8192
#define NL 4

// -------------------- scratch (device globals; no allocation allowed) ---------
__device__ float g_h  [BT*DM];
__device__ float g_q  [BT*DM];
__device__ float g_k  [BT*DM];
__device__ float g_v  [BT*DM];
__device__ float g_ov [BT*DM];
__device__ float g_y  [BT*DHid];
__device__ float g_tmp[BT*DM];
__device__ float g_wosum[DKk*DM];
__device__ int   g_is64;

// -------------------- helpers -------------------------------------------------
__device__ __forceinline__ float block_sum_256(float v, float* sbuf) {
    #pragma unroll
    for (int o = 16; o; o >>= 1) v += __shfl_xor_sync(0xffffffffu, v, o);
    int lane = threadIdx.x & 31, w = threadIdx.x >> 5;
    if (lane == 0) sbuf[w] = v;
    __syncthreads();
    if (threadIdx.x < 32) {
        float t = (lane < 8) ? sbuf[lane] : 0.f;
        #pragma unroll
        for (int o = 4; o; o >>= 1) t += __shfl_xor_sync(0xffffffffu, t, o);
        if (lane == 0) sbuf[0] = t;
    }
    __syncthreads();
    float r = sbuf[0];
    __syncthreads();
    return r;
}

// bf16x2 split: x -> hi(bf16) + lo(bf16 of residual). Packs 2 consecutive k
// elements into one u32 (low 16 bits = lower-k element), matching mma fragments.
__device__ __forceinline__ void pack_hilo(float x, float y, unsigned& hi, unsigned& lo) {
    __nv_bfloat16 hx = __float2bfloat16(x);
    __nv_bfloat16 hy = __float2bfloat16(y);
    float rx = x - __bfloat162float(hx);
    float ry = y - __bfloat162float(hy);
    __nv_bfloat16 lx = __float2bfloat16(rx);
    __nv_bfloat16 ly = __float2bfloat16(ry);
    hi = ((unsigned)__bfloat16_as_ushort(hy) << 16) | (unsigned)__bfloat16_as_ushort(hx);
    lo = ((unsigned)__bfloat16_as_ushort(ly) << 16) | (unsigned)__bfloat16_as_ushort(lx);
}

__device__ __forceinline__ void mma16816(float* c, const unsigned* a, const unsigned* b) {
    asm volatile(
        "mma.sync.aligned.m16n8k16.row.col.f32.bf16.bf16.f32 "
        "{%0,%1,%2,%3}, {%4,%5,%6,%7}, {%8,%9}, {%0,%1,%2,%3};\n"
        : "+f"(c[0]), "+f"(c[1]), "+f"(c[2]), "+f"(c[3])
        : "r"(a[0]), "r"(a[1]), "r"(a[2]), "r"(a[3]), "r"(b[0]), "r"(b[1]));
}

// -------------------- index dtype probe ---------------------------------------
__global__ void detect_idx(const int* __restrict__ xi) {
    __shared__ int ok;
    if (threadIdx.x == 0) ok = 1;
    __syncthreads();
    if (xi[2 * threadIdx.x + 1] != 0) atomicAnd(&ok, 0);
    __syncthreads();
    if (threadIdx.x == 0) g_is64 = ok;
}

// -------------------- embedding + layernorm -----------------------------------
__global__ __launch_bounds__(256) void embed_ln(const int* __restrict__ xi,
                                                const float* __restrict__ emb,
                                                const float* __restrict__ pos) {
    __shared__ float sbuf[32];
    int token = blockIdx.x;
    int t = token % TT;
    int d = threadIdx.x;
    int idx = g_is64 ? xi[2 * token] : xi[token];
    float val = emb[(size_t)idx * DM + d] + pos[(size_t)t * DM + d];
    float m = block_sum_256(val, sbuf) * (1.f / DM);
    float c = val - m;
    float var = block_sum_256(c * c, sbuf) * (1.f / DM);
    g_h[(size_t)token * DM + d] = c * rsqrtf(var + 1e-5f);
}

// -------------------- bf16x2 tensor-core GEMM 128x128x32 ----------------------
// D = A(fp32)[M][K] * B(fp32), computed as Ahi*Bhi + Ahi*Blo + Alo*Bhi in
// mma.sync.m16n8k16.bf16 with fp32 accumulators (~fp32 accuracy, tensor-pipe).
// BMODE 0: B row-major [K][N].  BMODE 1: B = per-head weights [n/32][K][n%32].
// EPI 0: C=acc.  EPI 1: C=relu(acc+bias[n]).  EPI 2: C=acc+bias[n].
template <int BMODE, int EPI>
__global__ __launch_bounds__(256) void mgemm(const float* __restrict__ A,
                                             const float* __restrict__ Bm,
                                             float* __restrict__ C,
                                             const float* __restrict__ bias,
                                             int M, int N, int K) {
    // u32 tiles of bf16x2 pairs along k. Row stride 20 u32 -> fragment LDS
    // banks (g*20 + t) mod 32 are all distinct across a warp (conflict-free).
    __shared__ unsigned As_hi[128][20];
    __shared__ unsigned As_lo[128][20];
    __shared__ unsigned Bs_hi[128][20];   // indexed [n][kpair]  (B transposed)
    __shared__ unsigned Bs_lo[128][20];

    const int bm = blockIdx.y * 128;
    const int bn = blockIdx.x * 128;
    const int tid  = threadIdx.x;
    const int wid  = tid >> 5;
    const int lane = tid & 31;
    const int g = lane >> 2;       // groupID (row within fragment)
    const int t = lane & 3;        // threadID in group (k-pair / col pos)
    const int wm = (wid & 3) * 32; // warp m offset (4 warps in m)
    const int wn = (wid >> 2) * 64;// warp n offset (2 warps in n)

    float acc[2][8][4];
    #pragma unroll
    for (int mt = 0; mt < 2; mt++)
        #pragma unroll
        for (int nt = 0; nt < 8; nt++)
            #pragma unroll
            for (int r = 0; r < 4; r++) acc[mt][nt][r] = 0.f;

    for (int k0 = 0; k0 < K; k0 += 32) {
        // ---- fill A tile: 128 rows x 32 k (8 float4 per row) ----
        #pragma unroll
        for (int it = 0; it < 4; it++) {
            int idx = it * 256 + tid;
            int m  = idx >> 3;
            int f4 = (idx & 7) * 4;       // k offset within tile
            float4 v = *(const float4*)(A + (size_t)(bm + m) * K + k0 + f4);
            unsigned h0, l0, h1, l1;
            pack_hilo(v.x, v.y, h0, l0);
            pack_hilo(v.z, v.w, h1, l1);
            int cp = f4 >> 1;             // kpair col (even)
            *(uint2*)&As_hi[m][cp] = make_uint2(h0, h1);
            *(uint2*)&As_lo[m][cp] = make_uint2(l0, l1);
        }
        // ---- fill B tile transposed: Bs[n][kpair], pairs along k ----
        #pragma unroll
        for (int it = 0; it < 8; it++) {
            int idx = it * 256 + tid;
            int kp = idx >> 7;            // 0..15
            int n  = idx & 127;
            int kk = k0 + kp * 2;
            float b0v, b1v;
            if (BMODE == 0) {
                const float* p = Bm + (size_t)kk * N + bn + n;
                b0v = p[0]; b1v = p[N];
            } else {
                int ng = bn + n;
                const float* p = Bm + (size_t)(ng >> 5) * ((size_t)K * 32)
                                    + (size_t)kk * 32 + (ng & 31);
                b0v = p[0]; b1v = p[32];
            }
            unsigned hh, ll;
            pack_hilo(b0v, b1v, hh, ll);
            Bs_hi[n][kp] = hh;
            Bs_lo[n][kp] = ll;
        }
        __syncthreads();

        // ---- compute: 2 k16 steps per tile ----
        #pragma unroll
        for (int ks = 0; ks < 2; ks++) {
            const int cb = ks * 8 + t;
            unsigned ah[2][4], al[2][4];
            #pragma unroll
            for (int mt = 0; mt < 2; mt++) {
                int r = wm + mt * 16;
                ah[mt][0] = As_hi[r + g    ][cb];
                ah[mt][1] = As_hi[r + g + 8][cb];
                ah[mt][2] = As_hi[r + g    ][cb + 4];
                ah[mt][3] = As_hi[r + g + 8][cb + 4];
                al[mt][0] = As_lo[r + g    ][cb];
                al[mt][1] = As_lo[r + g + 8][cb];
                al[mt][2] = As_lo[r + g    ][cb + 4];
                al[mt][3] = As_lo[r + g + 8][cb + 4];
            }
            #pragma unroll
            for (int nt = 0; nt < 8; nt++) {
                int col = wn + nt * 8 + g;
                unsigned bh[2], bl[2];
                bh[0] = Bs_hi[col][cb];  bh[1] = Bs_hi[col][cb + 4];
                bl[0] = Bs_lo[col][cb];  bl[1] = Bs_lo[col][cb + 4];
                #pragma unroll
                for (int mt = 0; mt < 2; mt++) {
                    mma16816(acc[mt][nt], ah[mt], bh);
                    mma16816(acc[mt][nt], ah[mt], bl);
                    mma16816(acc[mt][nt], al[mt], bh);
                }
            }
        }
        __syncthreads();
    }

    // ---- epilogue ----
    #pragma unroll
    for (int mt = 0; mt < 2; mt++) {
        #pragma unroll
        for (int nt = 0; nt < 8; nt++) {
            int row0 = bm + wm + mt * 16 + g;
            int col  = bn + wn + nt * 8 + 2 * t;
            float v0 = acc[mt][nt][0], v1 = acc[mt][nt][1];
            float v2 = acc[mt][nt][2], v3 = acc[mt][nt][3];
            if (EPI == 1) {
                float b0 = bias[col], b1 = bias[col + 1];
                v0 = fmaxf(v0 + b0, 0.f); v1 = fmaxf(v1 + b1, 0.f);
                v2 = fmaxf(v2 + b0, 0.f); v3 = fmaxf(v3 + b1, 0.f);
            }
            if (EPI == 2) {
                float b0 = bias[col], b1 = bias[col + 1];
                v0 += b0; v1 += b1; v2 += b0; v3 += b1;
            }
            *(float2*)(C + (size_t)row0 * N + col)       = make_float2(v0, v1);
            *(float2*)(C + (size_t)(row0 + 8) * N + col) = make_float2(v2, v3);
        }
    }
}

// -------------------- causal attention (exp-sum normalization) ----------------
__global__ __launch_bounds__(256) void attention(const float* __restrict__ q,
                                                 const float* __restrict__ k,
                                                 const float* __restrict__ v,
                                                 float* __restrict__ ov) {
    __shared__ float qs[64][33];
    __shared__ float ks[64][33];
    __shared__ float vs[64][33];
    __shared__ float s [64][65];

    const int bh = blockIdx.y;
    const int b  = bh >> 3, h = bh & 7;
    const int t0 = blockIdx.x * 64;
    const int tid = threadIdx.x;
    const int qi = tid >> 2;
    const int g  = tid & 3;

    for (int e = tid; e < 64 * 32; e += 256) {
        int r = e >> 5, d = e & 31;
        qs[r][d] = q[(size_t)(b * TT + t0 + r) * DM + h * DKk + d];
    }
    __syncthreads();

    float qreg[32];
    #pragma unroll
    for (int kk = 0; kk < 32; kk++) qreg[kk] = qs[qi][kk];

    float acc[8];
    #pragma unroll
    for (int j = 0; j < 8; j++) acc[j] = 0.f;
    float ssum = 0.f;

    const int tg = t0 + qi;

    for (int o0 = 0; o0 <= t0; o0 += 64) {
        for (int e = tid; e < 64 * 32; e += 256) {
            int r = e >> 5, d = e & 31;
            size_t gidx = (size_t)(b * TT + o0 + r) * DM + h * DKk + d;
            ks[r][d] = k[gidx];
            vs[r][d] = v[gidx];
        }
        __syncthreads();

        #pragma unroll 1
        for (int jj = 0; jj < 16; jj++) {
            int o = jj * 4 + g;
            float dot = 0.f;
            #pragma unroll
            for (int kk = 0; kk < 32; kk++) dot += qreg[kk] * ks[o][kk];
            float w = (o0 + o <= tg) ? __expf(fminf(dot, 50.f)) : 0.f;
            s[qi][o] = w;
        }
        __syncthreads();

        #pragma unroll 1
        for (int o = 0; o < 64; o++) {
            float w = s[qi][o];
            ssum += w;
            #pragma unroll
            for (int j = 0; j < 8; j++) acc[j] += w * vs[o][g * 8 + j];
        }
        __syncthreads();
    }

    float inv = 1.f / (ssum + 1e-10f);
    #pragma unroll
    for (int j = 0; j < 8; j++)
        ov[(size_t)(b * TT + tg) * DM + h * DKk + g * 8 + j] = acc[j] * inv;
}

// -------------------- sum wo over heads ---------------------------------------
__global__ void compute_wosum(const float* __restrict__ wo_layer) {
    int i = blockIdx.x * blockDim.x + threadIdx.x;
    if (i < DKk * DM) {
        float ssum = 0.f;
        #pragma unroll
        for (int hh = 0; hh < HH; hh++) ssum += wo_layer[(size_t)hh * DKk * DM + i];
        g_wosum[i] = ssum;
    }
}

// -------------------- fused: head-reduce + wo_sum proj + residual + LN --------
__global__ __launch_bounds__(256) void attn_out_ln(const float* __restrict__ ov) {
    __shared__ float row[DM];
    __shared__ float vsum[DKk];
    __shared__ float sbuf[32];
    int token = blockIdx.x;
    int d = threadIdx.x;
    row[d] = ov[(size_t)token * DM + d];
    __syncthreads();
    if (d < DKk) {
        float ssum = 0.f;
        #pragma unroll
        for (int hh = 0; hh < HH; hh++) ssum += row[hh * DKk + d];
        vsum[d] = ssum;
    }
    __syncthreads();
    float proj = 0.f;
    #pragma unroll
    for (int vv = 0; vv < DKk; vv++) proj += vsum[vv] * g_wosum[vv * DM + d];
    float val = g_h[(size_t)token * DM + d] + proj;
    float m = block_sum_256(val, sbuf) * (1.f / DM);
    float c = val - m;
    float var = block_sum_256(c * c, sbuf) * (1.f / DM);
    g_h[(size_t)token * DM + d] = c * rsqrtf(var + 1e-5f);
}

// -------------------- residual + LN -------------------------------------------
__global__ __launch_bounds__(256) void ln_residual(const float* __restrict__ add) {
    __shared__ float sbuf[32];
    int token = blockIdx.x;
    int d = threadIdx.x;
    float val = g_h[(size_t)token * DM + d] + add[(size_t)token * DM + d];
    float m = block_sum_256(val, sbuf) * (1.f / DM);
    float c = val - m;
    float var = block_sum_256(c * c, sbuf) * (1.f / DM);
    g_h[(size_t)token * DM + d] = c * rsqrtf(var + 1e-5f);
}

// -------------------- launch --------------------------------------------------
extern "C" void kernel_launch(void* const* d_in, const int* in_sizes, int n_in,
                              void* d_out, int out_size) {
    const int*   x     = (const int*)  d_in[0];
    const float* emb   = (const float*)d_in[1];
    const float* pos   = (const float*)d_in[2];
    const float* wq    = (const float*)d_in[3];
    const float* wk    = (const float*)d_in[4];
    const float* wv    = (const float*)d_in[5];
    const float* wo    = (const float*)d_in[6];
    const float* mlp0  = (const float*)d_in[7];
    const float* mlpb  = (const float*)d_in[8];
    const float* mlp1  = (const float*)d_in[9];
    const float* unemb = (const float*)d_in[10];
    const float* bias  = (const float*)d_in[11];
    float* out = (float*)d_out;

    float *h_, *q_, *k_, *v_, *ov_, *y_, *tmp_;
    cudaGetSymbolAddress((void**)&h_,   g_h);
    cudaGetSymbolAddress((void**)&q_,   g_q);
    cudaGetSymbolAddress((void**)&k_,   g_k);
    cudaGetSymbolAddress((void**)&v_,   g_v);
    cudaGetSymbolAddress((void**)&ov_,  g_ov);
    cudaGetSymbolAddress((void**)&y_,   g_y);
    cudaGetSymbolAddress((void**)&tmp_, g_tmp);

    detect_idx<<<1, 64>>>(x);
    embed_ln<<<BT, 256>>>(x, emb, pos);

    for (int l = 0; l < NL; l++) {
        const float* wql = wq + (size_t)l * HH * DM * DKk;
        const float* wkl = wk + (size_t)l * HH * DM * DKk;
        const float* wvl = wv + (size_t)l * HH * DM * DKk;
        const float* wol = wo + (size_t)l * HH * DKk * DM;

        compute_wosum<<<32, 256>>>(wol);

        dim3 gqkv(DM / 128, BT / 128);
        mgemm<1, 0><<<gqkv, 256>>>(h_, wql, q_, nullptr, BT, DM, DM);
        mgemm<1, 0><<<gqkv, 256>>>(h_, wkl, k_, nullptr, BT, DM, DM);
        mgemm<1, 0><<<gqkv, 256>>>(h_, wvl, v_, nullptr, BT, DM, DM);

        attention<<<dim3(TT / 64, BB * HH), 256>>>(q_, k_, v_, ov_);
        attn_out_ln<<<BT, 256>>>(ov_);

        mgemm<0, 1><<<dim3(DHid / 128, BT / 128), 256>>>(
            h_, mlp0 + (size_t)l * DM * DHid, y_, mlpb + (size_t)l * DHid, BT, DHid, DM);
        mgemm<0, 0><<<dim3(DM / 128, BT / 128), 256>>>(
            y_, mlp1 + (size_t)l * DHid * DM, tmp_, nullptr, BT, DM, DHid);
        ln_residual<<<BT, 256>>>(tmp_);
    }

    mgemm<0, 2><<<dim3(ND / 128, BT / 128), 256>>>(h_, unemb, out, bias, BT, ND, DM);
}

// round 3
// speedup vs baseline: 2.5741x; 2.1713x over previous
#include <cuda_runtime.h>
#include <cuda_bf16.h>
#include <math.h>

#define BB 4
#define TT 2048
#define BT (BB*TT)
#define DM 256
#define HH 8
#define DKk 32
#define DHid 1024
#define ND 8192
#define NL 4

#define KP_DM (DM/2)      // 128 pairs
#define KP_HID (DHid/2)   // 512 pairs

// packed-weight region offsets (u32 elements)
#define W_QKV 0
#define W_M0 (NL*3*DM*KP_DM)              // 393216
#define W_M1 (W_M0 + NL*DHid*KP_DM)       // 917504
#define W_UE (W_M1 + NL*DM*KP_HID)        // 1441792
#define W_TOT (W_UE + ND*KP_DM)           // 2490368

// -------------------- scratch (device globals; no allocation allowed) ---------
__device__ float    g_h  [BT*DM];
__device__ unsigned g_hh [BT*KP_DM];
__device__ unsigned g_hl [BT*KP_DM];
__device__ unsigned g_qh [BT*KP_DM];
__device__ unsigned g_ql [BT*KP_DM];
__device__ unsigned g_kh [BT*KP_DM];
__device__ unsigned g_kl [BT*KP_DM];
__device__ float    g_v  [BT*DM];
__device__ float    g_ov [BT*DM];
__device__ unsigned g_yh [BT*KP_HID];
__device__ unsigned g_yl [BT*KP_HID];
__device__ float    g_tmp[BT*DM];
__device__ unsigned g_wh [W_TOT];
__device__ unsigned g_wl [W_TOT];
__device__ float    g_wosum[NL*DKk*DM];
__device__ int      g_is64;

// -------------------- helpers -------------------------------------------------
__device__ __forceinline__ float block_sum_256(float v, float* sbuf) {
    #pragma unroll
    for (int o = 16; o; o >>= 1) v += __shfl_xor_sync(0xffffffffu, v, o);
    int lane = threadIdx.x & 31, w = threadIdx.x >> 5;
    if (lane == 0) sbuf[w] = v;
    __syncthreads();
    if (threadIdx.x < 32) {
        float t = (lane < 8) ? sbuf[lane] : 0.f;
        #pragma unroll
        for (int o = 4; o; o >>= 1) t += __shfl_xor_sync(0xffffffffu, t, o);
        if (lane == 0) sbuf[0] = t;
    }
    __syncthreads();
    float r = sbuf[0];
    __syncthreads();
    return r;
}

// fp32 -> bf16 hi + bf16 residual lo; packs 2 consecutive-k elements per u32.
__device__ __forceinline__ void pack_hilo(float x, float y, unsigned& hi, unsigned& lo) {
    __nv_bfloat16 hx = __float2bfloat16(x);
    __nv_bfloat16 hy = __float2bfloat16(y);
    float rx = x - __bfloat162float(hx);
    float ry = y - __bfloat162float(hy);
    __nv_bfloat16 lx = __float2bfloat16(rx);
    __nv_bfloat16 ly = __float2bfloat16(ry);
    hi = ((unsigned)__bfloat16_as_ushort(hy) << 16) | (unsigned)__bfloat16_as_ushort(hx);
    lo = ((unsigned)__bfloat16_as_ushort(ly) << 16) | (unsigned)__bfloat16_as_ushort(lx);
}

__device__ __forceinline__ void mma16816(float* c, const unsigned* a, const unsigned* b) {
    asm volatile(
        "mma.sync.aligned.m16n8k16.row.col.f32.bf16.bf16.f32 "
        "{%0,%1,%2,%3}, {%4,%5,%6,%7}, {%8,%9}, {%0,%1,%2,%3};\n"
        : "+f"(c[0]), "+f"(c[1]), "+f"(c[2]), "+f"(c[3])
        : "r"(a[0]), "r"(a[1]), "r"(a[2]), "r"(a[3]), "r"(b[0]), "r"(b[1]));
}

// -------------------- index dtype probe ---------------------------------------
__global__ void detect_idx(const int* __restrict__ xi) {
    __shared__ int ok;
    if (threadIdx.x == 0) ok = 1;
    __syncthreads();
    if (xi[2 * threadIdx.x + 1] != 0) atomicAnd(&ok, 0);
    __syncthreads();
    if (threadIdx.x == 0) g_is64 = ok;
}

// -------------------- one-shot weight pre-conversion --------------------------
// Packed-B layout is [KP][N] (kp-major): both reads and writes are coalesced.
__global__ __launch_bounds__(256) void convert_weights(
    const float* __restrict__ wq, const float* __restrict__ wk,
    const float* __restrict__ wv, const float* __restrict__ m0,
    const float* __restrict__ m1, const float* __restrict__ ue) {
    int i = blockIdx.x * 256 + threadIdx.x;
    if (i >= W_TOT) return;
    float a, b;
    if (i < W_M0) {                       // QKV: per-head [n/32][k][n%31] source
        int l3 = i >> 15;
        int r  = i & 32767;
        int kp = r >> 8;
        int n  = r & 255;
        int l = l3 / 3, mi = l3 % 3;
        const float* W = (mi == 0) ? wq : (mi == 1) ? wk : wv;
        size_t base = (size_t)l * HH * DM * DKk + (size_t)(n >> 5) * DM * DKk + (n & 31);
        a = W[base + (size_t)(2 * kp)     * DKk];
        b = W[base + (size_t)(2 * kp + 1) * DKk];
    } else if (i < W_M1) {                // mlp0 row-major [K][1024]
        int r = i - W_M0;
        int l = r >> 17;
        int rr = r & 131071;
        int kp = rr >> 10;
        int n  = rr & 1023;
        const float* W = m0 + (size_t)l * DM * DHid;
        a = W[(size_t)(2 * kp)     * DHid + n];
        b = W[(size_t)(2 * kp + 1) * DHid + n];
    } else if (i < W_UE) {                // mlp1 row-major [K][256]
        int r = i - W_M1;
        int l = r >> 17;
        int rr = r & 131071;
        int kp = rr >> 8;
        int n  = rr & 255;
        const float* W = m1 + (size_t)l * DHid * DM;
        a = W[(size_t)(2 * kp)     * DM + n];
        b = W[(size_t)(2 * kp + 1) * DM + n];
    } else {                              // unembedding [K][8192]
        int r = i - W_UE;
        int kp = r >> 13;
        int n  = r & 8191;
        a = ue[(size_t)(2 * kp)     * ND + n];
        b = ue[(size_t)(2 * kp + 1) * ND + n];
    }
    unsigned hi, lo;
    pack_hilo(a, b, hi, lo);
    g_wh[i] = hi;
    g_wl[i] = lo;
}

// -------------------- wo summed over heads, all layers -------------------------
__global__ void compute_wosum_all(const float* __restrict__ wo) {
    int i = blockIdx.x * 256 + threadIdx.x;
    if (i < NL * DKk * DM) {
        int l = i / (DKk * DM);
        int r = i % (DKk * DM);
        float s = 0.f;
        #pragma unroll
        for (int hh = 0; hh < HH; hh++)
            s += wo[(size_t)l * HH * DKk * DM + (size_t)hh * DKk * DM + r];
        g_wosum[i] = s;
    }
}

// -------------------- LN output -> fp32 h + packed hi/lo ----------------------
__device__ __forceinline__ void store_h_packed(int token, int d, float out) {
    g_h[(size_t)token * DM + d] = out;
    float other = __shfl_xor_sync(0xffffffffu, out, 1);
    if (!(d & 1)) {
        unsigned hi, lo;
        pack_hilo(out, other, hi, lo);
        g_hh[(size_t)token * KP_DM + (d >> 1)] = hi;
        g_hl[(size_t)token * KP_DM + (d >> 1)] = lo;
    }
}

// -------------------- embedding + layernorm -----------------------------------
__global__ __launch_bounds__(256) void embed_ln(const int* __restrict__ xi,
                                                const float* __restrict__ emb,
                                                const float* __restrict__ pos) {
    __shared__ float sbuf[32];
    int token = blockIdx.x;
    int t = token % TT;
    int d = threadIdx.x;
    int idx = g_is64 ? xi[2 * token] : xi[token];
    float val = emb[(size_t)idx * DM + d] + pos[(size_t)t * DM + d];
    float m = block_sum_256(val, sbuf) * (1.f / DM);
    float c = val - m;
    float var = block_sum_256(c * c, sbuf) * (1.f / DM);
    store_h_packed(token, d, c * rsqrtf(var + 1e-5f));
}

// -------------------- packed-operand tensor-core GEMM 128x128x32 --------------
// A: [M][KP] u32 hi/lo.  B: [KP][N] u32 hi/lo.
// EPI 0: fp32 C. EPI 1: relu(acc+bias) -> packed Ch/Cl. EPI 2: acc+bias fp32.
// EPI 3: acc -> packed Ch/Cl.
template <int EPI>
__global__ __launch_bounds__(256, 2) void mgemm_p(
    const unsigned* __restrict__ Ah, const unsigned* __restrict__ Al,
    const unsigned* __restrict__ Bh, const unsigned* __restrict__ Bl,
    float* __restrict__ C, unsigned* __restrict__ Ch, unsigned* __restrict__ Cl,
    const float* __restrict__ bias, int M, int N, int KP) {
    __shared__ unsigned As_hi[128][20];
    __shared__ unsigned As_lo[128][20];
    __shared__ unsigned Bs_hi[16][132];
    __shared__ unsigned Bs_lo[16][132];

    const int bm = blockIdx.y * 128;
    const int bn = blockIdx.x * 128;
    const int tid  = threadIdx.x;
    const int lane = tid & 31;
    const int wid  = tid >> 5;
    const int g = lane >> 2;
    const int t = lane & 3;
    const int wm = (wid & 3) * 32;
    const int wn = (wid >> 2) * 64;

    float acc[2][8][4];
    #pragma unroll
    for (int mt = 0; mt < 2; mt++)
        #pragma unroll
        for (int nt = 0; nt < 8; nt++)
            #pragma unroll
            for (int r = 0; r < 4; r++) acc[mt][nt][r] = 0.f;

    for (int kp0 = 0; kp0 < KP; kp0 += 16) {
        // A tile: 128 rows x 16 kpairs
        #pragma unroll
        for (int it = 0; it < 2; it++) {
            int i = it * 256 + tid;
            int m = i >> 2, c4 = (i & 3) * 4;
            uint4 vh = *(const uint4*)(Ah + (size_t)(bm + m) * KP + kp0 + c4);
            uint4 vl = *(const uint4*)(Al + (size_t)(bm + m) * KP + kp0 + c4);
            *(uint4*)&As_hi[m][c4] = vh;
            *(uint4*)&As_lo[m][c4] = vl;
        }
        // B tile: 16 kpairs x 128 n (conflict-free uint4 stores)
        #pragma unroll
        for (int it = 0; it < 2; it++) {
            int i = it * 256 + tid;
            int kp = i >> 5, n4 = (i & 31) * 4;
            uint4 vh = *(const uint4*)(Bh + (size_t)(kp0 + kp) * N + bn + n4);
            uint4 vl = *(const uint4*)(Bl + (size_t)(kp0 + kp) * N + bn + n4);
            *(uint4*)&Bs_hi[kp][n4] = vh;
            *(uint4*)&Bs_lo[kp][n4] = vl;
        }
        __syncthreads();

        #pragma unroll
        for (int ks = 0; ks < 2; ks++) {
            const int cb = ks * 8 + t;
            unsigned ah[2][4], al[2][4];
            #pragma unroll
            for (int mt = 0; mt < 2; mt++) {
                int r = wm + mt * 16;
                ah[mt][0] = As_hi[r + g    ][cb];
                ah[mt][1] = As_hi[r + g + 8][cb];
                ah[mt][2] = As_hi[r + g    ][cb + 4];
                ah[mt][3] = As_hi[r + g + 8][cb + 4];
                al[mt][0] = As_lo[r + g    ][cb];
                al[mt][1] = As_lo[r + g + 8][cb];
                al[mt][2] = As_lo[r + g    ][cb + 4];
                al[mt][3] = As_lo[r + g + 8][cb + 4];
            }
            #pragma unroll
            for (int nt = 0; nt < 8; nt++) {
                int col = wn + nt * 8 + g;
                unsigned bh[2], bl[2];
                bh[0] = Bs_hi[cb][col];     bh[1] = Bs_hi[cb + 4][col];
                bl[0] = Bs_lo[cb][col];     bl[1] = Bs_lo[cb + 4][col];
                #pragma unroll
                for (int mt = 0; mt < 2; mt++) {
                    mma16816(acc[mt][nt], ah[mt], bh);
                    mma16816(acc[mt][nt], ah[mt], bl);
                    mma16816(acc[mt][nt], al[mt], bh);
                }
            }
        }
        __syncthreads();
    }

    #pragma unroll
    for (int mt = 0; mt < 2; mt++) {
        #pragma unroll
        for (int nt = 0; nt < 8; nt++) {
            int row0 = bm + wm + mt * 16 + g;
            int col  = bn + wn + nt * 8 + 2 * t;
            float v0 = acc[mt][nt][0], v1 = acc[mt][nt][1];
            float v2 = acc[mt][nt][2], v3 = acc[mt][nt][3];
            if (EPI == 1) {
                float b0 = bias[col], b1 = bias[col + 1];
                v0 = fmaxf(v0 + b0, 0.f); v1 = fmaxf(v1 + b1, 0.f);
                v2 = fmaxf(v2 + b0, 0.f); v3 = fmaxf(v3 + b1, 0.f);
            }
            if (EPI == 2) {
                float b0 = bias[col], b1 = bias[col + 1];
                v0 += b0; v1 += b1; v2 += b0; v3 += b1;
            }
            if (EPI == 0 || EPI == 2) {
                *(float2*)(C + (size_t)row0 * N + col)       = make_float2(v0, v1);
                *(float2*)(C + (size_t)(row0 + 8) * N + col) = make_float2(v2, v3);
            } else {
                unsigned h0, l0, h1, l1;
                pack_hilo(v0, v1, h0, l0);
                pack_hilo(v2, v3, h1, l1);
                int NP = N >> 1, cp = col >> 1;
                Ch[(size_t)row0 * NP + cp]       = h0;
                Cl[(size_t)row0 * NP + cp]       = l0;
                Ch[(size_t)(row0 + 8) * NP + cp] = h1;
                Cl[(size_t)(row0 + 8) * NP + cp] = l1;
            }
        }
    }
}

// -------------------- tensor-core causal attention (exp-sum norm) --------------
// grid (TT/64, BB*HH), 256 thr = 8 warps: 4 m-tiles(16q) x 2 key-halves(32k).
__global__ __launch_bounds__(256, 2) void attention_mma(
    const unsigned* __restrict__ qh, const unsigned* __restrict__ ql,
    const unsigned* __restrict__ kh, const unsigned* __restrict__ kl,
    const float* __restrict__ v, float* __restrict__ ov) {
    __shared__ unsigned Ks_hi[64][20];
    __shared__ unsigned Ks_lo[64][20];
    __shared__ unsigned Vs_hi[32][36];
    __shared__ unsigned Vs_lo[32][36];
    __shared__ float    sOb[4][32][18];   // [warp-hi][lane][16 O + 2 rs]

    const int bh = blockIdx.y;
    const int b  = bh >> 3, h = bh & 7;
    const int t0 = blockIdx.x * 64;
    const int tid  = threadIdx.x;
    const int lane = tid & 31;
    const int wid  = tid >> 5;
    const int g = lane >> 2;
    const int t = lane & 3;
    const int wm = (wid & 3) * 16;   // query sub-tile
    const int nh = wid >> 2;         // key half

    // Q fragments (hi/lo), rows wm+g / wm+g+8, dk pairs
    unsigned qfh[2][4], qfl[2][4];
    {
        size_t base = (size_t)(b * TT + t0 + wm) * KP_DM + h * 16;
        #pragma unroll
        for (int ks = 0; ks < 2; ks++) {
            qfh[ks][0] = qh[base + (size_t)g * KP_DM + ks * 8 + t];
            qfh[ks][1] = qh[base + (size_t)(g + 8) * KP_DM + ks * 8 + t];
            qfh[ks][2] = qh[base + (size_t)g * KP_DM + ks * 8 + t + 4];
            qfh[ks][3] = qh[base + (size_t)(g + 8) * KP_DM + ks * 8 + t + 4];
            qfl[ks][0] = ql[base + (size_t)g * KP_DM + ks * 8 + t];
            qfl[ks][1] = ql[base + (size_t)(g + 8) * KP_DM + ks * 8 + t];
            qfl[ks][2] = ql[base + (size_t)g * KP_DM + ks * 8 + t + 4];
            qfl[ks][3] = ql[base + (size_t)(g + 8) * KP_DM + ks * 8 + t + 4];
        }
    }

    float o[4][4];
    #pragma unroll
    for (int nf = 0; nf < 4; nf++)
        #pragma unroll
        for (int r = 0; r < 4; r++) o[nf][r] = 0.f;
    float rs0 = 0.f, rs1 = 0.f;

    const int row0 = t0 + wm + g;
    const int row1 = row0 + 8;

    for (int o0 = 0; o0 <= t0; o0 += 64) {
        // K tile (already packed in global)
        for (int i = tid; i < 1024; i += 256) {
            int key = i >> 4, kp = i & 15;
            size_t gi = (size_t)(b * TT + o0 + key) * KP_DM + h * 16 + kp;
            Ks_hi[key][kp] = kh[gi];
            Ks_lo[key][kp] = kl[gi];
        }
        // V tile: transpose to [vdim][keypair] + pack
        for (int i = tid; i < 1024; i += 256) {
            int vd = i & 31, kp = i >> 5;
            size_t gi = (size_t)(b * TT + o0 + 2 * kp) * DM + h * DKk + vd;
            float v0 = v[gi], v1 = v[gi + DM];
            unsigned hh, ll;
            pack_hilo(v0, v1, hh, ll);
            Vs_hi[vd][kp] = hh;
            Vs_lo[vd][kp] = ll;
        }
        __syncthreads();

        // S = Q K^T (16 rows x 32 keys per warp), bf16x2 split
        float c[4][4];
        #pragma unroll
        for (int j = 0; j < 4; j++)
            #pragma unroll
            for (int r = 0; r < 4; r++) c[j][r] = 0.f;
        #pragma unroll
        for (int j = 0; j < 4; j++) {
            int col = nh * 32 + j * 8 + g;
            #pragma unroll
            for (int ks = 0; ks < 2; ks++) {
                unsigned bhf[2], blf[2];
                bhf[0] = Ks_hi[col][ks * 8 + t];
                bhf[1] = Ks_hi[col][ks * 8 + t + 4];
                blf[0] = Ks_lo[col][ks * 8 + t];
                blf[1] = Ks_lo[col][ks * 8 + t + 4];
                mma16816(c[j], qfh[ks], bhf);
                mma16816(c[j], qfh[ks], blf);
                mma16816(c[j], qfl[ks], bhf);
            }
        }

        // mask + exp + rowsum
        #pragma unroll
        for (int j = 0; j < 4; j++) {
            int cb = o0 + nh * 32 + j * 8 + 2 * t;
            c[j][0] = (cb     <= row0) ? __expf(fminf(c[j][0], 50.f)) : 0.f;
            c[j][1] = (cb + 1 <= row0) ? __expf(fminf(c[j][1], 50.f)) : 0.f;
            c[j][2] = (cb     <= row1) ? __expf(fminf(c[j][2], 50.f)) : 0.f;
            c[j][3] = (cb + 1 <= row1) ? __expf(fminf(c[j][3], 50.f)) : 0.f;
            rs0 += c[j][0] + c[j][1];
            rs1 += c[j][2] + c[j][3];
        }

        // O += P V  (register repack of C-fragment into A-fragment)
        #pragma unroll
        for (int klq = 0; klq < 2; klq++) {
            unsigned ph[4], pl[4];
            pack_hilo(c[2 * klq][0],     c[2 * klq][1],     ph[0], pl[0]);
            pack_hilo(c[2 * klq][2],     c[2 * klq][3],     ph[1], pl[1]);
            pack_hilo(c[2 * klq + 1][0], c[2 * klq + 1][1], ph[2], pl[2]);
            pack_hilo(c[2 * klq + 1][2], c[2 * klq + 1][3], ph[3], pl[3]);
            int kb = (nh * 2 + klq) * 8;
            #pragma unroll
            for (int nf = 0; nf < 4; nf++) {
                int vc = nf * 8 + g;
                unsigned vhf[2], vlf[2];
                vhf[0] = Vs_hi[vc][kb + t];
                vhf[1] = Vs_hi[vc][kb + t + 4];
                vlf[0] = Vs_lo[vc][kb + t];
                vlf[1] = Vs_lo[vc][kb + t + 4];
                mma16816(o[nf], ph, vhf);
                mma16816(o[nf], ph, vlf);
                mma16816(o[nf], pl, vhf);
            }
        }
        __syncthreads();
    }

    // reduce rowsums over t (lanes within group)
    rs0 += __shfl_xor_sync(0xffffffffu, rs0, 1);
    rs0 += __shfl_xor_sync(0xffffffffu, rs0, 2);
    rs1 += __shfl_xor_sync(0xffffffffu, rs1, 1);
    rs1 += __shfl_xor_sync(0xffffffffu, rs1, 2);

    // combine key-halves: warps 4-7 dump, warps 0-3 merge + write
    if (wid >= 4) {
        #pragma unroll
        for (int nf = 0; nf < 4; nf++)
            #pragma unroll
            for (int r = 0; r < 4; r++) sOb[wid - 4][lane][nf * 4 + r] = o[nf][r];
        sOb[wid - 4][lane][16] = rs0;
        sOb[wid - 4][lane][17] = rs1;
    }
    __syncthreads();
    if (wid < 4) {
        #pragma unroll
        for (int nf = 0; nf < 4; nf++)
            #pragma unroll
            for (int r = 0; r < 4; r++) o[nf][r] += sOb[wid][lane][nf * 4 + r];
        rs0 += sOb[wid][lane][16];
        rs1 += sOb[wid][lane][17];
        float i0 = 1.f / (rs0 + 1e-10f);
        float i1 = 1.f / (rs1 + 1e-10f);
        size_t r0 = (size_t)(b * TT + row0);
        #pragma unroll
        for (int nf = 0; nf < 4; nf++) {
            int vd = h * DKk + nf * 8 + 2 * t;
            *(float2*)(ov + r0 * DM + vd)       = make_float2(o[nf][0] * i0, o[nf][1] * i0);
            *(float2*)(ov + (r0 + 8) * DM + vd) = make_float2(o[nf][2] * i1, o[nf][3] * i1);
        }
    }
}

// -------------------- fused: head-reduce + wo_sum proj + residual + LN --------
__global__ __launch_bounds__(256) void attn_out_ln(const float* __restrict__ ov,
                                                   const float* __restrict__ wos) {
    __shared__ float row[DM];
    __shared__ float vsum[DKk];
    __shared__ float sbuf[32];
    int token = blockIdx.x;
    int d = threadIdx.x;
    row[d] = ov[(size_t)token * DM + d];
    __syncthreads();
    if (d < DKk) {
        float ssum = 0.f;
        #pragma unroll
        for (int hh = 0; hh < HH; hh++) ssum += row[hh * DKk + d];
        vsum[d] = ssum;
    }
    __syncthreads();
    float proj = 0.f;
    #pragma unroll
    for (int vv = 0; vv < DKk; vv++) proj += vsum[vv] * wos[vv * DM + d];
    float val = g_h[(size_t)token * DM + d] + proj;
    float m = block_sum_256(val, sbuf) * (1.f / DM);
    float c = val - m;
    float var = block_sum_256(c * c, sbuf) * (1.f / DM);
    store_h_packed(token, d, c * rsqrtf(var + 1e-5f));
}

// -------------------- residual + LN -------------------------------------------
__global__ __launch_bounds__(256) void ln_residual(const float* __restrict__ add) {
    __shared__ float sbuf[32];
    int token = blockIdx.x;
    int d = threadIdx.x;
    float val = g_h[(size_t)token * DM + d] + add[(size_t)token * DM + d];
    float m = block_sum_256(val, sbuf) * (1.f / DM);
    float c = val - m;
    float var = block_sum_256(c * c, sbuf) * (1.f / DM);
    store_h_packed(token, d, c * rsqrtf(var + 1e-5f));
}

// -------------------- launch --------------------------------------------------
extern "C" void kernel_launch(void* const* d_in, const int* in_sizes, int n_in,
                              void* d_out, int out_size) {
    const int*   x     = (const int*)  d_in[0];
    const float* emb   = (const float*)d_in[1];
    const float* pos   = (const float*)d_in[2];
    const float* wq    = (const float*)d_in[3];
    const float* wk    = (const float*)d_in[4];
    const float* wv    = (const float*)d_in[5];
    const float* wo    = (const float*)d_in[6];
    const float* mlp0  = (const float*)d_in[7];
    const float* mlpb  = (const float*)d_in[8];
    const float* mlp1  = (const float*)d_in[9];
    const float* unemb = (const float*)d_in[10];
    const float* bias  = (const float*)d_in[11];
    float* out = (float*)d_out;

    unsigned *hh_, *hl_, *qh_, *ql_, *kh_, *kl_, *yh_, *yl_, *wh_, *wl_;
    float *v_, *ov_, *tmp_, *wos_;
    cudaGetSymbolAddress((void**)&hh_, g_hh);
    cudaGetSymbolAddress((void**)&hl_, g_hl);
    cudaGetSymbolAddress((void**)&qh_, g_qh);
    cudaGetSymbolAddress((void**)&ql_, g_ql);
    cudaGetSymbolAddress((void**)&kh_, g_kh);
    cudaGetSymbolAddress((void**)&kl_, g_kl);
    cudaGetSymbolAddress((void**)&yh_, g_yh);
    cudaGetSymbolAddress((void**)&yl_, g_yl);
    cudaGetSymbolAddress((void**)&wh_, g_wh);
    cudaGetSymbolAddress((void**)&wl_, g_wl);
    cudaGetSymbolAddress((void**)&v_,   g_v);
    cudaGetSymbolAddress((void**)&ov_,  g_ov);
    cudaGetSymbolAddress((void**)&tmp_, g_tmp);
    cudaGetSymbolAddress((void**)&wos_, g_wosum);

    detect_idx<<<1, 64>>>(x);
    convert_weights<<<(W_TOT + 255) / 256, 256>>>(wq, wk, wv, mlp0, mlp1, unemb);
    compute_wosum_all<<<(NL * DKk * DM + 255) / 256, 256>>>(wo);
    embed_ln<<<BT, 256>>>(x, emb, pos);

    for (int l = 0; l < NL; l++) {
        const unsigned* wqh = wh_ + (size_t)(l * 3 + 0) * DM * KP_DM;
        const unsigned* wqlp= wl_ + (size_t)(l * 3 + 0) * DM * KP_DM;
        const unsigned* wkh = wh_ + (size_t)(l * 3 + 1) * DM * KP_DM;
        const unsigned* wklp= wl_ + (size_t)(l * 3 + 1) * DM * KP_DM;
        const unsigned* wvh = wh_ + (size_t)(l * 3 + 2) * DM * KP_DM;
        const unsigned* wvlp= wl_ + (size_t)(l * 3 + 2) * DM * KP_DM;
        const unsigned* m0h = wh_ + W_M0 + (size_t)l * DHid * KP_DM;
        const unsigned* m0l = wl_ + W_M0 + (size_t)l * DHid * KP_DM;
        const unsigned* m1h = wh_ + W_M1 + (size_t)l * DM * KP_HID;
        const unsigned* m1l = wl_ + W_M1 + (size_t)l * DM * KP_HID;

        dim3 gqkv(DM / 128, BT / 128);
        mgemm_p<3><<<gqkv, 256>>>(hh_, hl_, wqh, wqlp, nullptr, qh_, ql_, nullptr, BT, DM, KP_DM);
        mgemm_p<3><<<gqkv, 256>>>(hh_, hl_, wkh, wklp, nullptr, kh_, kl_, nullptr, BT, DM, KP_DM);
        mgemm_p<0><<<gqkv, 256>>>(hh_, hl_, wvh, wvlp, v_, nullptr, nullptr, nullptr, BT, DM, KP_DM);

        attention_mma<<<dim3(TT / 64, BB * HH), 256>>>(qh_, ql_, kh_, kl_, v_, ov_);
        attn_out_ln<<<BT, 256>>>(ov_, wos_ + (size_t)l * DKk * DM);

        mgemm_p<1><<<dim3(DHid / 128, BT / 128), 256>>>(
            hh_, hl_, m0h, m0l, nullptr, yh_, yl_, mlpb + (size_t)l * DHid, BT, DHid, KP_DM);
        mgemm_p<0><<<dim3(DM / 128, BT / 128), 256>>>(
            yh_, yl_, m1h, m1l, tmp_, nullptr, nullptr, nullptr, BT, DM, KP_HID);
        ln_residual<<<BT, 256>>>(tmp_);
    }

    mgemm_p<2><<<dim3(ND / 128, BT / 128), 256>>>(
        hh_, hl_, wh_ + W_UE, wl_ + W_UE, out, nullptr, nullptr, bias, BT, ND, KP_DM);
}

// round 4
// speedup vs baseline: 3.3131x; 1.2871x over previous
#include <cuda_runtime.h>
#include <cuda_bf16.h>
#include <math.h>

#define BB 4
#define TT 2048
#define BT (BB*TT)
#define DM 256
#define HH 8
#define DKk 32
#define DHid 1024
#define ND 8192
#define NL 4

#define KP_DM (DM/2)      // 128 pairs
#define KP_HID (DHid/2)   // 512 pairs

// packed-weight region offsets (u32 elements)
#define W_M0 (NL*3*DM*KP_DM)
#define W_M1 (W_M0 + NL*DHid*KP_DM)
#define W_UE (W_M1 + NL*DM*KP_HID)
#define W_TOT (W_UE + ND*KP_DM)

// -------------------- scratch (device globals) ---------------------------------
__device__ float    g_h  [BT*DM];
__device__ unsigned g_hh [BT*KP_DM];
__device__ unsigned g_hl [BT*KP_DM];
__device__ unsigned g_qh [BT*KP_DM];
__device__ unsigned g_ql [BT*KP_DM];
__device__ unsigned g_kh [BT*KP_DM];
__device__ unsigned g_kl [BT*KP_DM];
__device__ float    g_v  [BT*DM];
__device__ unsigned g_vth[BT*KP_DM];   // V transposed+packed: [bh][vd0..31][kp0..1023]
__device__ unsigned g_vtl[BT*KP_DM];
__device__ float    g_ov [BT*DM];
__device__ unsigned g_yh [BT*KP_HID];
__device__ unsigned g_yl [BT*KP_HID];
__device__ float    g_tmp[BT*DM];
__device__ unsigned g_wh [W_TOT];
__device__ unsigned g_wl [W_TOT];
__device__ float    g_wosum[NL*DKk*DM];
__device__ int      g_is64;

// -------------------- helpers -------------------------------------------------
__device__ __forceinline__ void pack_hilo(float x, float y, unsigned& hi, unsigned& lo) {
    __nv_bfloat16 hx = __float2bfloat16(x);
    __nv_bfloat16 hy = __float2bfloat16(y);
    float rx = x - __bfloat162float(hx);
    float ry = y - __bfloat162float(hy);
    __nv_bfloat16 lx = __float2bfloat16(rx);
    __nv_bfloat16 ly = __float2bfloat16(ry);
    hi = ((unsigned)__bfloat16_as_ushort(hy) << 16) | (unsigned)__bfloat16_as_ushort(hx);
    lo = ((unsigned)__bfloat16_as_ushort(ly) << 16) | (unsigned)__bfloat16_as_ushort(lx);
}

__device__ __forceinline__ void mma16816(float* c, const unsigned* a, const unsigned* b) {
    asm volatile(
        "mma.sync.aligned.m16n8k16.row.col.f32.bf16.bf16.f32 "
        "{%0,%1,%2,%3}, {%4,%5,%6,%7}, {%8,%9}, {%0,%1,%2,%3};\n"
        : "+f"(c[0]), "+f"(c[1]), "+f"(c[2]), "+f"(c[3])
        : "r"(a[0]), "r"(a[1]), "r"(a[2]), "r"(a[3]), "r"(b[0]), "r"(b[1]));
}

__device__ __forceinline__ void cp16(void* sdst, const void* gsrc) {
    unsigned sa = (unsigned)__cvta_generic_to_shared(sdst);
    asm volatile("cp.async.cg.shared.global [%0], [%1], 16;\n" :: "r"(sa), "l"(gsrc));
}
#define CP_COMMIT() asm volatile("cp.async.commit_group;\n" ::: "memory")
template <int N> __device__ __forceinline__ void cp_wait() {
    asm volatile("cp.async.wait_group %0;\n" :: "n"(N) : "memory");
}

__device__ __forceinline__ float warp_sum(float v) {
    #pragma unroll
    for (int o = 16; o; o >>= 1) v += __shfl_xor_sync(0xffffffffu, v, o);
    return v;
}

// -------------------- index dtype probe ---------------------------------------
__global__ void detect_idx(const int* __restrict__ xi) {
    __shared__ int ok;
    if (threadIdx.x == 0) ok = 1;
    __syncthreads();
    if (xi[2 * threadIdx.x + 1] != 0) atomicAnd(&ok, 0);
    __syncthreads();
    if (threadIdx.x == 0) g_is64 = ok;
}

// -------------------- one-shot weight pre-conversion --------------------------
__global__ __launch_bounds__(256) void convert_weights(
    const float* __restrict__ wq, const float* __restrict__ wk,
    const float* __restrict__ wv, const float* __restrict__ m0,
    const float* __restrict__ m1, const float* __restrict__ ue) {
    int i = blockIdx.x * 256 + threadIdx.x;
    if (i >= W_TOT) return;
    float a, b;
    if (i < W_M0) {                       // QKV per-head [n/32][k][n%32] source
        int l3 = i >> 15;
        int r  = i & 32767;
        int kp = r >> 8;
        int n  = r & 255;
        int l = l3 / 3, mi = l3 % 3;
        const float* W = (mi == 0) ? wq : (mi == 1) ? wk : wv;
        size_t base = (size_t)l * HH * DM * DKk + (size_t)(n >> 5) * DM * DKk + (n & 31);
        a = W[base + (size_t)(2 * kp)     * DKk];
        b = W[base + (size_t)(2 * kp + 1) * DKk];
    } else if (i < W_M1) {
        int r = i - W_M0;
        int l = r >> 17;
        int rr = r & 131071;
        int kp = rr >> 10;
        int n  = rr & 1023;
        const float* W = m0 + (size_t)l * DM * DHid;
        a = W[(size_t)(2 * kp)     * DHid + n];
        b = W[(size_t)(2 * kp + 1) * DHid + n];
    } else if (i < W_UE) {
        int r = i - W_M1;
        int l = r >> 17;
        int rr = r & 131071;
        int kp = rr >> 8;
        int n  = rr & 255;
        const float* W = m1 + (size_t)l * DHid * DM;
        a = W[(size_t)(2 * kp)     * DM + n];
        b = W[(size_t)(2 * kp + 1) * DM + n];
    } else {
        int r = i - W_UE;
        int kp = r >> 13;
        int n  = r & 8191;
        a = ue[(size_t)(2 * kp)     * ND + n];
        b = ue[(size_t)(2 * kp + 1) * ND + n];
    }
    unsigned hi, lo;
    pack_hilo(a, b, hi, lo);
    g_wh[i] = hi;
    g_wl[i] = lo;
}

// -------------------- wo summed over heads, all layers -------------------------
__global__ void compute_wosum_all(const float* __restrict__ wo) {
    int i = blockIdx.x * 256 + threadIdx.x;
    if (i < NL * DKk * DM) {
        int l = i / (DKk * DM);
        int r = i % (DKk * DM);
        float s = 0.f;
        #pragma unroll
        for (int hh = 0; hh < HH; hh++)
            s += wo[(size_t)l * HH * DKk * DM + (size_t)hh * DKk * DM + r];
        g_wosum[i] = s;
    }
}

// -------------------- warp-per-token LN core -----------------------------------
// val[j] holds dim d = j*32 + lane. Writes fp32 h + packed hh/hl.
__device__ __forceinline__ void ln_store_warp(int token, int lane, float* val) {
    float s = 0.f;
    #pragma unroll
    for (int j = 0; j < 8; j++) s += val[j];
    s = warp_sum(s);
    float m = s * (1.f / DM);
    float vv = 0.f;
    #pragma unroll
    for (int j = 0; j < 8; j++) { val[j] -= m; vv += val[j] * val[j]; }
    vv = warp_sum(vv);
    float inv = rsqrtf(vv * (1.f / DM) + 1e-5f);
    #pragma unroll
    for (int j = 0; j < 8; j++) {
        float out = val[j] * inv;
        int d = j * 32 + lane;
        g_h[(size_t)token * DM + d] = out;
        float other = __shfl_xor_sync(0xffffffffu, out, 1);
        if (!(lane & 1)) {
            unsigned hi, lo;
            pack_hilo(out, other, hi, lo);
            g_hh[(size_t)token * KP_DM + j * 16 + (lane >> 1)] = hi;
            g_hl[(size_t)token * KP_DM + j * 16 + (lane >> 1)] = lo;
        }
    }
}

// -------------------- embedding + layernorm (warp/token) ----------------------
__global__ __launch_bounds__(256) void embed_ln_w(const int* __restrict__ xi,
                                                  const float* __restrict__ emb,
                                                  const float* __restrict__ pos) {
    int token = blockIdx.x * 8 + (threadIdx.x >> 5);
    int lane = threadIdx.x & 31;
    int t = token % TT;
    int idx = g_is64 ? xi[2 * token] : xi[token];
    float val[8];
    #pragma unroll
    for (int j = 0; j < 8; j++) {
        int d = j * 32 + lane;
        val[j] = emb[(size_t)idx * DM + d] + pos[(size_t)t * DM + d];
    }
    ln_store_warp(token, lane, val);
}

// -------------------- head-reduce + wo proj + residual + LN (warp/token) -------
__global__ __launch_bounds__(256) void attn_out_ln_w(const float* __restrict__ ov,
                                                     const float* __restrict__ wos) {
    int token = blockIdx.x * 8 + (threadIdx.x >> 5);
    int lane = threadIdx.x & 31;
    float vs = 0.f;
    float val[8];
    #pragma unroll
    for (int j = 0; j < 8; j++) {
        float o = ov[(size_t)token * DM + j * 32 + lane];
        vs += o;                          // vsum[lane] = sum over heads (j)
        val[j] = g_h[(size_t)token * DM + j * 32 + lane];
    }
    #pragma unroll
    for (int v = 0; v < DKk; v++) {
        float sv = __shfl_sync(0xffffffffu, vs, v);
        #pragma unroll
        for (int j = 0; j < 8; j++) val[j] += sv * wos[v * DM + j * 32 + lane];
    }
    ln_store_warp(token, lane, val);
}

// -------------------- residual + LN (warp/token) -------------------------------
__global__ __launch_bounds__(256) void ln_residual_w(const float* __restrict__ add) {
    int token = blockIdx.x * 8 + (threadIdx.x >> 5);
    int lane = threadIdx.x & 31;
    float val[8];
    #pragma unroll
    for (int j = 0; j < 8; j++) {
        int d = j * 32 + lane;
        val[j] = g_h[(size_t)token * DM + d] + add[(size_t)token * DM + d];
    }
    ln_store_warp(token, lane, val);
}

// -------------------- packed-operand tensor-core GEMM 128xBNx32 ---------------
// EPI 0: fp32 C. EPI 1: relu(acc+bias)->packed Ch/Cl. EPI 2: acc+bias fp32.
// EPI 4: fused QKV (blockIdx.x>>1 selects matrix; q->Ch/Cl, k->Ch2/Cl2, v->C).
template <int EPI, int BN>
__global__ __launch_bounds__(256, 2) void mgemm_p(
    const unsigned* __restrict__ Ah, const unsigned* __restrict__ Al,
    const unsigned* __restrict__ Bh, const unsigned* __restrict__ Bl,
    float* __restrict__ C, unsigned* __restrict__ Ch, unsigned* __restrict__ Cl,
    unsigned* __restrict__ Ch2, unsigned* __restrict__ Cl2,
    const float* __restrict__ bias, int M, int N, int KP) {
    const int NT = BN / 16;
    __shared__ unsigned As_hi[128][20];
    __shared__ unsigned As_lo[128][20];
    __shared__ unsigned Bs_hi[16][BN + 4];
    __shared__ unsigned Bs_lo[16][BN + 4];

    const int bm = blockIdx.y * 128;
    int bn, mat = 0;
    if (EPI == 4) {
        mat = blockIdx.x >> 1;
        bn = (blockIdx.x & 1) * 128;
        Bh += (size_t)mat * DM * KP_DM;
        Bl += (size_t)mat * DM * KP_DM;
    } else {
        bn = blockIdx.x * BN;
    }
    const int tid  = threadIdx.x;
    const int lane = tid & 31;
    const int wid  = tid >> 5;
    const int g = lane >> 2;
    const int t = lane & 3;
    const int wm = (wid & 3) * 32;
    const int wn = (wid >> 2) * (BN / 2);

    float acc[2][NT][4];
    #pragma unroll
    for (int mt = 0; mt < 2; mt++)
        #pragma unroll
        for (int nt = 0; nt < NT; nt++)
            #pragma unroll
            for (int r = 0; r < 4; r++) acc[mt][nt][r] = 0.f;

    for (int kp0 = 0; kp0 < KP; kp0 += 16) {
        #pragma unroll
        for (int it = 0; it < 2; it++) {
            int i = it * 256 + tid;
            int m = i >> 2, c4 = (i & 3) * 4;
            uint4 vh = *(const uint4*)(Ah + (size_t)(bm + m) * KP + kp0 + c4);
            uint4 vl = *(const uint4*)(Al + (size_t)(bm + m) * KP + kp0 + c4);
            *(uint4*)&As_hi[m][c4] = vh;
            *(uint4*)&As_lo[m][c4] = vl;
        }
        #pragma unroll
        for (int it = 0; it < BN / 64; it++) {
            int i = it * 256 + tid;
            int kp = i / (BN / 4), n4 = (i % (BN / 4)) * 4;
            uint4 vh = *(const uint4*)(Bh + (size_t)(kp0 + kp) * N + bn + n4);
            uint4 vl = *(const uint4*)(Bl + (size_t)(kp0 + kp) * N + bn + n4);
            *(uint4*)&Bs_hi[kp][n4] = vh;
            *(uint4*)&Bs_lo[kp][n4] = vl;
        }
        __syncthreads();

        #pragma unroll
        for (int ks = 0; ks < 2; ks++) {
            const int cb = ks * 8 + t;
            unsigned ah[2][4], al[2][4];
            #pragma unroll
            for (int mt = 0; mt < 2; mt++) {
                int r = wm + mt * 16;
                ah[mt][0] = As_hi[r + g    ][cb];
                ah[mt][1] = As_hi[r + g + 8][cb];
                ah[mt][2] = As_hi[r + g    ][cb + 4];
                ah[mt][3] = As_hi[r + g + 8][cb + 4];
                al[mt][0] = As_lo[r + g    ][cb];
                al[mt][1] = As_lo[r + g + 8][cb];
                al[mt][2] = As_lo[r + g    ][cb + 4];
                al[mt][3] = As_lo[r + g + 8][cb + 4];
            }
            #pragma unroll
            for (int nt = 0; nt < NT; nt++) {
                int col = wn + nt * 8 + g;
                unsigned bh[2], bl[2];
                bh[0] = Bs_hi[cb][col];     bh[1] = Bs_hi[cb + 4][col];
                bl[0] = Bs_lo[cb][col];     bl[1] = Bs_lo[cb + 4][col];
                #pragma unroll
                for (int mt = 0; mt < 2; mt++) {
                    mma16816(acc[mt][nt], ah[mt], bh);
                    mma16816(acc[mt][nt], ah[mt], bl);
                    mma16816(acc[mt][nt], al[mt], bh);
                }
            }
        }
        __syncthreads();
    }

    #pragma unroll
    for (int mt = 0; mt < 2; mt++) {
        #pragma unroll
        for (int nt = 0; nt < NT; nt++) {
            int row0 = bm + wm + mt * 16 + g;
            int col  = bn + wn + nt * 8 + 2 * t;
            float v0 = acc[mt][nt][0], v1 = acc[mt][nt][1];
            float v2 = acc[mt][nt][2], v3 = acc[mt][nt][3];
            if (EPI == 1) {
                float b0 = bias[col], b1 = bias[col + 1];
                v0 = fmaxf(v0 + b0, 0.f); v1 = fmaxf(v1 + b1, 0.f);
                v2 = fmaxf(v2 + b0, 0.f); v3 = fmaxf(v3 + b1, 0.f);
            }
            if (EPI == 2) {
                float b0 = bias[col], b1 = bias[col + 1];
                v0 += b0; v1 += b1; v2 += b0; v3 += b1;
            }
            bool fp32out = (EPI == 0 || EPI == 2 || (EPI == 4 && mat == 2));
            if (fp32out) {
                *(float2*)(C + (size_t)row0 * N + col)       = make_float2(v0, v1);
                *(float2*)(C + (size_t)(row0 + 8) * N + col) = make_float2(v2, v3);
            } else {
                unsigned* Dh = (EPI == 4 && mat == 1) ? Ch2 : Ch;
                unsigned* Dl = (EPI == 4 && mat == 1) ? Cl2 : Cl;
                unsigned h0, l0, h1, l1;
                pack_hilo(v0, v1, h0, l0);
                pack_hilo(v2, v3, h1, l1);
                int NP = N >> 1, cp = col >> 1;
                Dh[(size_t)row0 * NP + cp]       = h0;
                Dl[(size_t)row0 * NP + cp]       = l0;
                Dh[(size_t)(row0 + 8) * NP + cp] = h1;
                Dl[(size_t)(row0 + 8) * NP + cp] = l1;
            }
        }
    }
}

// -------------------- V transpose + pack ---------------------------------------
// v fp32 [token][DM] -> vth/vtl [bh][vd 0..31][kp 0..TT/2-1]
__global__ __launch_bounds__(256) void pack_v(const float* __restrict__ v,
                                              unsigned* __restrict__ vth,
                                              unsigned* __restrict__ vtl) {
    __shared__ float s[64][33];
    const int bh = blockIdx.y;
    const int b = bh >> 3, h = bh & 7;
    const int k0 = blockIdx.x * 64;
    const int tid = threadIdx.x;
    for (int i = tid; i < 2048; i += 256) {
        int key = i >> 5, vd = i & 31;
        s[key][vd] = v[(size_t)(b * TT + k0 + key) * DM + h * DKk + vd];
    }
    __syncthreads();
    for (int i = tid; i < 1024; i += 256) {
        int vd = i >> 5, kp = i & 31;
        unsigned hi, lo;
        pack_hilo(s[2 * kp][vd], s[2 * kp + 1][vd], hi, lo);
        size_t o = ((size_t)bh * DKk + vd) * (TT / 2) + (k0 >> 1) + kp;
        vth[o] = hi;
        vtl[o] = lo;
    }
}

// -------------------- tensor-core causal attention -----------------------------
// 128-query blocks, 8 warps = 8 m-tiles of 16 queries over all 64 keys/tile.
// cp.async double-buffered K/V tiles; block order reversed for causal balance.
__global__ __launch_bounds__(256, 2) void attention_mma2(
    const unsigned* __restrict__ qh, const unsigned* __restrict__ ql,
    const unsigned* __restrict__ kh, const unsigned* __restrict__ kl,
    const unsigned* __restrict__ vth, const unsigned* __restrict__ vtl,
    float* __restrict__ ov) {
    __shared__ unsigned Ks_hi[2][64][20];
    __shared__ unsigned Ks_lo[2][64][20];
    __shared__ unsigned Vs_hi[2][32][36];
    __shared__ unsigned Vs_lo[2][32][36];

    const int bh = blockIdx.y;
    const int b  = bh >> 3, h = bh & 7;
    const int t0 = (gridDim.x - 1 - blockIdx.x) * 128;   // big work first
    const int tid  = threadIdx.x;
    const int lane = tid & 31;
    const int wid  = tid >> 5;
    const int g = lane >> 2;
    const int t = lane & 3;
    const int wm = wid * 16;

    // Q fragments
    unsigned qfh[2][4], qfl[2][4];
    {
        size_t base = (size_t)(b * TT + t0 + wm) * KP_DM + h * 16;
        #pragma unroll
        for (int ks = 0; ks < 2; ks++) {
            qfh[ks][0] = qh[base + (size_t)g * KP_DM + ks * 8 + t];
            qfh[ks][1] = qh[base + (size_t)(g + 8) * KP_DM + ks * 8 + t];
            qfh[ks][2] = qh[base + (size_t)g * KP_DM + ks * 8 + t + 4];
            qfh[ks][3] = qh[base + (size_t)(g + 8) * KP_DM + ks * 8 + t + 4];
            qfl[ks][0] = ql[base + (size_t)g * KP_DM + ks * 8 + t];
            qfl[ks][1] = ql[base + (size_t)(g + 8) * KP_DM + ks * 8 + t];
            qfl[ks][2] = ql[base + (size_t)g * KP_DM + ks * 8 + t + 4];
            qfl[ks][3] = ql[base + (size_t)(g + 8) * KP_DM + ks * 8 + t + 4];
        }
    }

    float o[4][4];
    #pragma unroll
    for (int nf = 0; nf < 4; nf++)
        #pragma unroll
        for (int r = 0; r < 4; r++) o[nf][r] = 0.f;
    float rs0 = 0.f, rs1 = 0.f;

    const int row0 = t0 + wm + g;
    const int row1 = row0 + 8;
    const int nit = t0 / 64 + 2;

    // tile-load lambda via macro-ish inline
    const int kkey = tid >> 2, kseg = tid & 3;    // K: 64 keys x 4 uint4
    const int vvd  = tid >> 3, vseg = tid & 7;    // V: 32 vd x 8 uint4

    #define ISSUE_TILE(s, o0)                                                        \
        do {                                                                          \
            size_t kgi = (size_t)(b * TT + (o0) + kkey) * KP_DM + h * 16 + kseg * 4;  \
            cp16(&Ks_hi[s][kkey][kseg * 4], kh + kgi);                                \
            cp16(&Ks_lo[s][kkey][kseg * 4], kl + kgi);                                \
            size_t vgi = ((size_t)bh * DKk + vvd) * (TT / 2) + ((o0) >> 1) + vseg * 4;\
            cp16(&Vs_hi[s][vvd][vseg * 4], vth + vgi);                                \
            cp16(&Vs_lo[s][vvd][vseg * 4], vtl + vgi);                                \
        } while (0)

    ISSUE_TILE(0, 0);
    CP_COMMIT();

    for (int it = 0; it < nit; it++) {
        const int o0 = it * 64;
        const int s = it & 1;
        if (it + 1 < nit) {
            ISSUE_TILE(s ^ 1, o0 + 64);
            CP_COMMIT();
            cp_wait<1>();
        } else {
            cp_wait<0>();
        }
        __syncthreads();

        if (o0 <= t0 + wm + 15) {
            // S = Q K^T : 16 q-rows x 64 keys
            float c[8][4];
            #pragma unroll
            for (int j = 0; j < 8; j++)
                #pragma unroll
                for (int r = 0; r < 4; r++) c[j][r] = 0.f;
            #pragma unroll
            for (int j = 0; j < 8; j++) {
                int col = j * 8 + g;
                #pragma unroll
                for (int ks = 0; ks < 2; ks++) {
                    unsigned bhf[2], blf[2];
                    bhf[0] = Ks_hi[s][col][ks * 8 + t];
                    bhf[1] = Ks_hi[s][col][ks * 8 + t + 4];
                    blf[0] = Ks_lo[s][col][ks * 8 + t];
                    blf[1] = Ks_lo[s][col][ks * 8 + t + 4];
                    mma16816(c[j], qfh[ks], bhf);
                    mma16816(c[j], qfh[ks], blf);
                    mma16816(c[j], qfl[ks], bhf);
                }
            }
            // mask + exp + rowsum
            #pragma unroll
            for (int j = 0; j < 8; j++) {
                int cb = o0 + j * 8 + 2 * t;
                c[j][0] = (cb     <= row0) ? __expf(fminf(c[j][0], 50.f)) : 0.f;
                c[j][1] = (cb + 1 <= row0) ? __expf(fminf(c[j][1], 50.f)) : 0.f;
                c[j][2] = (cb     <= row1) ? __expf(fminf(c[j][2], 50.f)) : 0.f;
                c[j][3] = (cb + 1 <= row1) ? __expf(fminf(c[j][3], 50.f)) : 0.f;
                rs0 += c[j][0] + c[j][1];
                rs1 += c[j][2] + c[j][3];
            }
            // O += P V
            #pragma unroll
            for (int klq = 0; klq < 4; klq++) {
                unsigned ph[4], pl[4];
                pack_hilo(c[2 * klq][0],     c[2 * klq][1],     ph[0], pl[0]);
                pack_hilo(c[2 * klq][2],     c[2 * klq][3],     ph[1], pl[1]);
                pack_hilo(c[2 * klq + 1][0], c[2 * klq + 1][1], ph[2], pl[2]);
                pack_hilo(c[2 * klq + 1][2], c[2 * klq + 1][3], ph[3], pl[3]);
                int kb = klq * 8;
                #pragma unroll
                for (int nf = 0; nf < 4; nf++) {
                    int vc = nf * 8 + g;
                    unsigned vhf[2], vlf[2];
                    vhf[0] = Vs_hi[s][vc][kb + t];
                    vhf[1] = Vs_hi[s][vc][kb + t + 4];
                    vlf[0] = Vs_lo[s][vc][kb + t];
                    vlf[1] = Vs_lo[s][vc][kb + t + 4];
                    mma16816(o[nf], ph, vhf);
                    mma16816(o[nf], ph, vlf);
                    mma16816(o[nf], pl, vhf);
                }
            }
        }
        __syncthreads();
    }
    #undef ISSUE_TILE

    rs0 += __shfl_xor_sync(0xffffffffu, rs0, 1);
    rs0 += __shfl_xor_sync(0xffffffffu, rs0, 2);
    rs1 += __shfl_xor_sync(0xffffffffu, rs1, 1);
    rs1 += __shfl_xor_sync(0xffffffffu, rs1, 2);
    float i0 = 1.f / (rs0 + 1e-10f);
    float i1 = 1.f / (rs1 + 1e-10f);
    size_t r0 = (size_t)(b * TT + row0);
    #pragma unroll
    for (int nf = 0; nf < 4; nf++) {
        int vd = h * DKk + nf * 8 + 2 * t;
        *(float2*)(ov + r0 * DM + vd)       = make_float2(o[nf][0] * i0, o[nf][1] * i0);
        *(float2*)(ov + (r0 + 8) * DM + vd) = make_float2(o[nf][2] * i1, o[nf][3] * i1);
    }
}

// -------------------- launch --------------------------------------------------
extern "C" void kernel_launch(void* const* d_in, const int* in_sizes, int n_in,
                              void* d_out, int out_size) {
    const int*   x     = (const int*)  d_in[0];
    const float* emb   = (const float*)d_in[1];
    const float* pos   = (const float*)d_in[2];
    const float* wq    = (const float*)d_in[3];
    const float* wk    = (const float*)d_in[4];
    const float* wv    = (const float*)d_in[5];
    const float* wo    = (const float*)d_in[6];
    const float* mlp0  = (const float*)d_in[7];
    const float* mlpb  = (const float*)d_in[8];
    const float* mlp1  = (const float*)d_in[9];
    const float* unemb = (const float*)d_in[10];
    const float* bias  = (const float*)d_in[11];
    float* out = (float*)d_out;

    unsigned *hh_, *hl_, *qh_, *ql_, *kh_, *kl_, *yh_, *yl_, *wh_, *wl_, *vth_, *vtl_;
    float *v_, *ov_, *tmp_, *wos_;
    cudaGetSymbolAddress((void**)&hh_, g_hh);
    cudaGetSymbolAddress((void**)&hl_, g_hl);
    cudaGetSymbolAddress((void**)&qh_, g_qh);
    cudaGetSymbolAddress((void**)&ql_, g_ql);
    cudaGetSymbolAddress((void**)&kh_, g_kh);
    cudaGetSymbolAddress((void**)&kl_, g_kl);
    cudaGetSymbolAddress((void**)&yh_, g_yh);
    cudaGetSymbolAddress((void**)&yl_, g_yl);
    cudaGetSymbolAddress((void**)&wh_, g_wh);
    cudaGetSymbolAddress((void**)&wl_, g_wl);
    cudaGetSymbolAddress((void**)&vth_, g_vth);
    cudaGetSymbolAddress((void**)&vtl_, g_vtl);
    cudaGetSymbolAddress((void**)&v_,   g_v);
    cudaGetSymbolAddress((void**)&ov_,  g_ov);
    cudaGetSymbolAddress((void**)&tmp_, g_tmp);
    cudaGetSymbolAddress((void**)&wos_, g_wosum);

    detect_idx<<<1, 64>>>(x);
    convert_weights<<<(W_TOT + 255) / 256, 256>>>(wq, wk, wv, mlp0, mlp1, unemb);
    compute_wosum_all<<<(NL * DKk * DM + 255) / 256, 256>>>(wo);
    embed_ln_w<<<BT / 8, 256>>>(x, emb, pos);

    for (int l = 0; l < NL; l++) {
        const unsigned* wqkv_h = wh_ + (size_t)(l * 3) * DM * KP_DM;
        const unsigned* wqkv_l = wl_ + (size_t)(l * 3) * DM * KP_DM;
        const unsigned* m0h = wh_ + W_M0 + (size_t)l * DHid * KP_DM;
        const unsigned* m0l = wl_ + W_M0 + (size_t)l * DHid * KP_DM;
        const unsigned* m1h = wh_ + W_M1 + (size_t)l * DM * KP_HID;
        const unsigned* m1l = wl_ + W_M1 + (size_t)l * DM * KP_HID;

        mgemm_p<4, 128><<<dim3(6, BT / 128), 256>>>(
            hh_, hl_, wqkv_h, wqkv_l, v_, qh_, ql_, kh_, kl_, nullptr, BT, DM, KP_DM);
        pack_v<<<dim3(TT / 64, BB * HH), 256>>>(v_, vth_, vtl_);

        attention_mma2<<<dim3(TT / 128, BB * HH), 256>>>(qh_, ql_, kh_, kl_, vth_, vtl_, ov_);
        attn_out_ln_w<<<BT / 8, 256>>>(ov_, wos_ + (size_t)l * DKk * DM);

        mgemm_p<1, 128><<<dim3(DHid / 128, BT / 128), 256>>>(
            hh_, hl_, m0h, m0l, nullptr, yh_, yl_, nullptr, nullptr,
            mlpb + (size_t)l * DHid, BT, DHid, KP_DM);
        mgemm_p<0, 64><<<dim3(DM / 64, BT / 128), 256>>>(
            yh_, yl_, m1h, m1l, tmp_, nullptr, nullptr, nullptr, nullptr,
            nullptr, BT, DM, KP_HID);
        ln_residual_w<<<BT / 8, 256>>>(tmp_);
    }

    mgemm_p<2, 128><<<dim3(ND / 128, BT / 128), 256>>>(
        hh_, hl_, wh_ + W_UE, wl_ + W_UE, out, nullptr, nullptr, nullptr, nullptr,
        bias, BT, ND, KP_DM);
}